// round 14
// baseline (speedup 1.0000x reference)
#include <cuda_runtime.h>
#include <cuda_fp16.h>
#include <math.h>
#include <stdint.h>

// ---------------- problem constants ----------------
#define HDIM   768
#define SEQ    256
#define BATCH  16
#define LAYERS 12
#define HEADS  12
#define DHEAD  64
#define FF     3072
#define NTOK   4096      // BATCH*SEQ
#define NLBL   9

// ---------------- device scratch (static; allocation-guard safe) --------
__device__ float  g_x   [NTOK * HDIM];
__device__ __half g_xh  [NTOK * HDIM];
__device__ __half g_qh  [NTOK * HDIM];
__device__ __half g_kh  [NTOK * HDIM];
__device__ __half g_vh  [NTOK * HDIM];
__device__ __half g_ch  [NTOK * HDIM];     // attention context, fp16
__device__ float  g_tmp [NTOK * HDIM];
__device__ __half g_fh  [NTOK * FF];       // FFN hidden, fp16
__device__ float  g_comp[NTOK * HDIM];

// fp16 weights, plain [L][K][N] layout (pure cast of the fp32 inputs)
#define HH (LAYERS * HDIM * HDIM)
#define HF (LAYERS * HDIM * FF)
#define WQ_OFF  0
#define WK_OFF  (HH)
#define WV_OFF  (2 * HH)
#define WO_OFF  (3 * HH)
#define W1_OFF  (4 * HH)
#define W2_OFF  (4 * HH + HF)
__device__ __half g_wh[4 * HH + 2 * HF];

// ---------------- helpers ------------------------------------------------
__device__ __forceinline__ float gelu_tanh(float x) {
    float x3 = x * x * x;
    float t  = tanhf(0.7978845608028654f * (x + 0.044715f * x3));
    return 0.5f * x * (1.0f + t);
}

__device__ __forceinline__ uint32_t pack2(float lo, float hi) {
    uint32_t u;
    asm("cvt.rn.f16x2.f32 %0, %1, %2;" : "=r"(u) : "f"(hi), "f"(lo));
    return u;
}

__device__ __forceinline__ void mma_f16(float* c, const uint32_t* a, const uint32_t* b) {
    asm volatile(
        "mma.sync.aligned.m16n8k16.row.col.f32.f16.f16.f32 "
        "{%0,%1,%2,%3}, {%4,%5,%6,%7}, {%8,%9}, {%0,%1,%2,%3};\n"
        : "+f"(c[0]), "+f"(c[1]), "+f"(c[2]), "+f"(c[3])
        : "r"(a[0]), "r"(a[1]), "r"(a[2]), "r"(a[3]), "r"(b[0]), "r"(b[1]));
}

__device__ __forceinline__ void cp_async16(uint32_t dst, const void* src) {
    asm volatile("cp.async.cg.shared.global [%0], [%1], 16;\n" :: "r"(dst), "l"(src));
}

__device__ __forceinline__ void ldsm_x4(uint32_t* r, uint32_t addr) {
    asm volatile(
        "ldmatrix.sync.aligned.m8n8.x4.shared.b16 {%0,%1,%2,%3}, [%4];"
        : "=r"(r[0]), "=r"(r[1]), "=r"(r[2]), "=r"(r[3]) : "r"(addr));
}

__device__ __forceinline__ void ldsm_x4_t(uint32_t* r, uint32_t addr) {
    asm volatile(
        "ldmatrix.sync.aligned.m8n8.x4.trans.shared.b16 {%0,%1,%2,%3}, [%4];"
        : "=r"(r[0]), "=r"(r[1]), "=r"(r[2]), "=r"(r[3]) : "r"(addr));
}

// ---------------- weight conversion: fp32 -> fp16 (fused, 2 launches) ----
__global__ __launch_bounds__(256)
void convw4_kernel(const float* __restrict__ W0, const float* __restrict__ W1_,
                   const float* __restrict__ W2_, const float* __restrict__ W3,
                   __half* __restrict__ P) {
    const int half_hh = HH / 2;
    for (int i = blockIdx.x * blockDim.x + threadIdx.x; i < 4 * half_hh;
         i += gridDim.x * blockDim.x) {
        const int reg = i / half_hh;
        const int off = i - reg * half_hh;
        const float* W = (reg == 0) ? W0 : (reg == 1) ? W1_ : (reg == 2) ? W2_ : W3;
        float2 v = ((const float2*)W)[off];
        ((uint32_t*)P)[i] = pack2(v.x, v.y);
    }
}

__global__ __launch_bounds__(256)
void convw2_kernel(const float* __restrict__ W0, const float* __restrict__ W1_,
                   __half* __restrict__ P) {
    const int half_hf = HF / 2;
    for (int i = blockIdx.x * blockDim.x + threadIdx.x; i < 2 * half_hf;
         i += gridDim.x * blockDim.x) {
        const int reg = i / half_hf;
        const int off = i - reg * half_hf;
        const float* W = (reg == 0) ? W0 : W1_;
        float2 v = ((const float2*)W)[off];
        ((uint32_t*)P)[i] = pack2(v.x, v.y);
    }
}

// ---------------- FP16 GEMM: 4 warps x 64x64, cp.async 6-stage -----------
// CTA tile 128x128, 128 threads, warp grid 2x2, warp tile 64x64.
// Same swizzled smem layout as validated rounds; MMA:LDSM ratio 4.0.
#define BM 128
#define BN 128
#define A_BYTES 8192
#define ST_BYTES 16384
#define NSTAGES 6
#define GEMM_SMEM (NSTAGES * ST_BYTES)    // 98304 B

__device__ __forceinline__ uint32_t swA(int r, int u) {
    return (uint32_t)(r * 64 + ((u ^ ((r >> 1) & 3)) << 4));
}
__device__ __forceinline__ uint32_t swB(int k, int u) {
    return (uint32_t)(A_BYTES + k * 256 + ((u ^ (k & 7)) << 4));
}

// EPI: 1 = +bias, 2 = +bias+gelu, 3 = +bias+residual
// OUTH: 0 = fp32 C, 1 = fp16 H
template<int EPI, int OUTH>
__global__ __launch_bounds__(128, 2)
void gemm_kernel(int M, int N, int K,
                 const __half* __restrict__ A,
                 const __half* __restrict__ B0,
                 const __half* __restrict__ B1,
                 const __half* __restrict__ B2,
                 const float* __restrict__ bias0,
                 const float* __restrict__ bias1,
                 const float* __restrict__ bias2,
                 const float* __restrict__ RES,
                 float* __restrict__ C0,
                 float* __restrict__ C1,
                 float* __restrict__ C2,
                 __half* __restrict__ H0,
                 __half* __restrict__ H1,
                 __half* __restrict__ H2) {
    extern __shared__ __align__(128) uint8_t smraw[];
    const uint32_t smem_base = (uint32_t)__cvta_generic_to_shared(smraw);

    const int z = blockIdx.z;
    const __half* Bp  = (z == 0) ? B0 : ((z == 1) ? B1 : B2);
    const float* bias = (z == 0) ? bias0 : ((z == 1) ? bias1 : bias2);
    float* C          = (z == 0) ? C0 : ((z == 1) ? C1 : C2);
    __half* H         = (z == 0) ? H0 : ((z == 1) ? H1 : H2);

    const int tid  = threadIdx.x;        // 0..127
    const int bx   = blockIdx.x;
    const int by   = blockIdx.y;
    const int wid  = tid >> 5;           // 0..3
    const int lane = tid & 31;
    const int g    = lane >> 2;
    const int t    = lane & 3;

    const int warp_m = (wid >> 1) * 64;  // 0 or 64
    const int warp_n = (wid & 1)  * 64;  // 0 or 64

    // loaders: A = one row (tid) x 4 units; B = k-row (tid>>2) x 4 units
    const int bkr = tid >> 2;            // 0..31
    const int bu0 = (tid & 3) * 4;       // 0,4,8,12

    const __half* Asrc = A + (size_t)(by * BM + tid) * K;
    const __half* Bsrc = Bp + (size_t)bkr * N + bx * BN + bu0 * 8;

    uint32_t dA[4], dB[4];
    #pragma unroll
    for (int u = 0; u < 4; u++) dA[u] = swA(tid, u);
    #pragma unroll
    for (int j = 0; j < 4; j++) dB[j] = swB(bkr, bu0 + j);

    float acc[4][8][4];
    #pragma unroll
    for (int i = 0; i < 4; i++)
        #pragma unroll
        for (int j = 0; j < 8; j++)
            #pragma unroll
            for (int r = 0; r < 4; r++) acc[i][j][r] = 0.0f;

    auto issue = [&](int kt, int st) {
        const uint32_t sb = smem_base + st * ST_BYTES;
        const __half* Ak = Asrc + (size_t)kt * 32;
        const __half* Bk = Bsrc + (size_t)(kt * 32) * N;
        #pragma unroll
        for (int u = 0; u < 4; u++)
            cp_async16(sb + dA[u], Ak + u * 8);
        #pragma unroll
        for (int j = 0; j < 4; j++)
            cp_async16(sb + dB[j], Bk + j * 8);
        asm volatile("cp.async.commit_group;\n");
    };

    const int aRowL = warp_m + (lane & 15);
    const int aUHi  = lane >> 4;
    const int bKL = (lane & 7) + ((lane >> 3) & 1) * 8;
    const int bUL = (warp_n >> 3) + ((lane >> 4) & 1);

    auto process = [&](uint32_t sb) {
        #pragma unroll
        for (int kg = 0; kg < 2; kg++) {
            uint32_t af[4][4];
            uint32_t bf[8][2];
            #pragma unroll
            for (int mi = 0; mi < 4; mi++) {
                const int r = aRowL + mi * 16;
                ldsm_x4(af[mi], sb + swA(r, kg * 2 + aUHi));
            }
            #pragma unroll
            for (int njp = 0; njp < 4; njp++) {
                uint32_t br[4];
                const int k = kg * 16 + bKL;
                ldsm_x4_t(br, sb + swB(k, bUL + njp * 2));
                bf[njp * 2    ][0] = br[0]; bf[njp * 2    ][1] = br[1];
                bf[njp * 2 + 1][0] = br[2]; bf[njp * 2 + 1][1] = br[3];
            }
            #pragma unroll
            for (int mi = 0; mi < 4; mi++)
                #pragma unroll
                for (int nj = 0; nj < 8; nj++)
                    mma_f16(acc[mi][nj], af[mi], bf[nj]);
        }
    };

    const int nk = K >> 5;    // 24 or 96, always even, >= 6
    issue(0, 0);
    issue(1, 1);
    issue(2, 2);
    issue(3, 3);

    for (int kt = 0; kt < nk; kt += 2) {
        if (kt + 2 < nk) asm volatile("cp.async.wait_group 2;\n");
        else             asm volatile("cp.async.wait_group 0;\n");
        __syncthreads();
        if (kt + 4 < nk) {
            issue(kt + 4, (kt + 4) % NSTAGES);
            issue(kt + 5, (kt + 5) % NSTAGES);
        }
        process(smem_base + (kt % NSTAGES) * ST_BYTES);
        process(smem_base + ((kt + 1) % NSTAGES) * ST_BYTES);
    }

    // ---- epilogue ----
    #pragma unroll
    for (int mi = 0; mi < 4; mi++) {
        const int r0 = by * BM + warp_m + mi * 16 + g;
        #pragma unroll
        for (int nj = 0; nj < 8; nj++) {
            const int c0 = bx * BN + warp_n + nj * 8 + 2 * t;
            float v0 = acc[mi][nj][0];
            float v1 = acc[mi][nj][1];
            float v2 = acc[mi][nj][2];
            float v3 = acc[mi][nj][3];
            {
                float bb0 = bias[c0], bb1 = bias[c0 + 1];
                v0 += bb0; v1 += bb1; v2 += bb0; v3 += bb1;
            }
            if (EPI == 2) {
                v0 = gelu_tanh(v0); v1 = gelu_tanh(v1);
                v2 = gelu_tanh(v2); v3 = gelu_tanh(v3);
            }
            if (EPI == 3) {
                v0 += RES[(size_t)(r0    ) * N + c0    ];
                v1 += RES[(size_t)(r0    ) * N + c0 + 1];
                v2 += RES[(size_t)(r0 + 8) * N + c0    ];
                v3 += RES[(size_t)(r0 + 8) * N + c0 + 1];
            }
            if (OUTH) {
                *(uint32_t*)&H[(size_t)(r0    ) * N + c0] = pack2(v0, v1);
                *(uint32_t*)&H[(size_t)(r0 + 8) * N + c0] = pack2(v2, v3);
            } else {
                C[(size_t)(r0    ) * N + c0    ] = v0;
                C[(size_t)(r0    ) * N + c0 + 1] = v1;
                C[(size_t)(r0 + 8) * N + c0    ] = v2;
                C[(size_t)(r0 + 8) * N + c0 + 1] = v3;
            }
        }
    }
}

// ---------------- tensor-core attention (2 CTAs per (b,h)) ---------------
#define ATT_Q  0
#define ATT_K  32768
#define ATT_V  65536
#define ATT_MB 98304
#define ATT_SMEM2 (98304 + 1024)

__device__ __forceinline__ uint32_t swz128(int r, int u) {
    return (uint32_t)(r * 128 + ((u ^ (r & 7)) << 4));
}

__global__ __launch_bounds__(128, 2)
void attn_mma_kernel(const __half* __restrict__ Q,
                     const __half* __restrict__ K,
                     const __half* __restrict__ V,
                     const int* __restrict__ mask,
                     __half* __restrict__ O) {
    extern __shared__ __align__(128) uint8_t smraw[];
    const uint32_t sb = (uint32_t)__cvta_generic_to_shared(smraw);
    float* mb = (float*)(smraw + ATT_MB);

    const int bx   = blockIdx.x;
    const int bh   = bx >> 1;
    const int half = bx & 1;
    const int b    = bh / HEADS;
    const int h    = bh % HEADS;
    const int tid  = threadIdx.x;
    const int wid  = tid >> 5;
    const int lane = tid & 31;
    const int g    = lane >> 2;
    const int t    = lane & 3;

    {
        const int u  = tid & 7;
        const int r0 = tid >> 3;               // 0..15
        #pragma unroll
        for (int i = 0; i < 16; i++) {
            const int r = r0 + i * 16;
            const size_t goff = (size_t)(b * SEQ + r) * HDIM + h * DHEAD + u * 8;
            cp_async16(sb + ATT_K + swz128(r, u), K + goff);
            cp_async16(sb + ATT_V + swz128(r, u), V + goff);
        }
        #pragma unroll
        for (int i = 0; i < 8; i++) {
            const int rq = r0 + i * 16;        // 0..127 local
            const size_t goff =
                (size_t)(b * SEQ + half * 128 + rq) * HDIM + h * DHEAD + u * 8;
            cp_async16(sb + ATT_Q + swz128(rq, u), Q + goff);
        }
        asm volatile("cp.async.commit_group;\n");
    }
    mb[tid]       = mask[b * SEQ + tid]       ? 0.0f : -10000.0f;
    mb[tid + 128] = mask[b * SEQ + tid + 128] ? 0.0f : -10000.0f;
    asm volatile("cp.async.wait_group 0;\n");
    __syncthreads();

    const int warp_q = wid * 32;               // local Q row base

    uint32_t qf[2][4][4];
    #pragma unroll
    for (int mi = 0; mi < 2; mi++)
        #pragma unroll
        for (int kg = 0; kg < 4; kg++)
            ldsm_x4(qf[mi][kg],
                sb + ATT_Q + swz128(warp_q + mi * 16 + (lane & 15),
                                    kg * 2 + (lane >> 4)));

    float acc_o[2][8][4];
    #pragma unroll
    for (int mi = 0; mi < 2; mi++)
        #pragma unroll
        for (int nj = 0; nj < 8; nj++)
            #pragma unroll
            for (int r = 0; r < 4; r++) acc_o[mi][nj][r] = 0.0f;
    float zz[4] = {0.f, 0.f, 0.f, 0.f};

    for (int kc = 0; kc < 4; kc++) {
        const int key0 = kc * 64;
        float s[2][8][4];
        #pragma unroll
        for (int mi = 0; mi < 2; mi++)
            #pragma unroll
            for (int nj = 0; nj < 8; nj++)
                #pragma unroll
                for (int r = 0; r < 4; r++) s[mi][nj][r] = 0.0f;

        #pragma unroll
        for (int kg = 0; kg < 4; kg++) {
            uint32_t kf[4][4];
            #pragma unroll
            for (int njp = 0; njp < 4; njp++) {
                const int r = key0 + njp * 16 + (lane & 7) + 8 * ((lane >> 4) & 1);
                const int u = kg * 2 + ((lane >> 3) & 1);
                ldsm_x4(kf[njp], sb + ATT_K + swz128(r, u));
            }
            #pragma unroll
            for (int mi = 0; mi < 2; mi++)
                #pragma unroll
                for (int njp = 0; njp < 4; njp++) {
                    mma_f16(s[mi][njp * 2    ], qf[mi][kg], &kf[njp][0]);
                    mma_f16(s[mi][njp * 2 + 1], qf[mi][kg], &kf[njp][2]);
                }
        }

        uint32_t pf[2][4][4];
        #pragma unroll
        for (int mi = 0; mi < 2; mi++) {
            #pragma unroll
            for (int nj = 0; nj < 8; nj++) {
                const float m0 = mb[key0 + nj * 8 + 2 * t];
                const float m1 = mb[key0 + nj * 8 + 2 * t + 1];
                float p0 = __expf(s[mi][nj][0] * 0.125f + m0);
                float p1 = __expf(s[mi][nj][1] * 0.125f + m1);
                float p2 = __expf(s[mi][nj][2] * 0.125f + m0);
                float p3 = __expf(s[mi][nj][3] * 0.125f + m1);
                zz[mi * 2    ] += p0 + p1;
                zz[mi * 2 + 1] += p2 + p3;
                const int kg2 = nj >> 1;
                const int hi  = nj & 1;
                pf[mi][kg2][hi * 2    ] = pack2(p0, p1);
                pf[mi][kg2][hi * 2 + 1] = pack2(p2, p3);
            }
        }

        #pragma unroll
        for (int kg2 = 0; kg2 < 4; kg2++) {
            uint32_t vf[4][4];
            #pragma unroll
            for (int njp = 0; njp < 4; njp++) {
                const int r = key0 + kg2 * 16 + (lane & 7) + 8 * ((lane >> 3) & 1);
                const int u = njp * 2 + ((lane >> 4) & 1);
                ldsm_x4_t(vf[njp], sb + ATT_V + swz128(r, u));
            }
            #pragma unroll
            for (int mi = 0; mi < 2; mi++)
                #pragma unroll
                for (int njp = 0; njp < 4; njp++) {
                    mma_f16(acc_o[mi][njp * 2    ], pf[mi][kg2], &vf[njp][0]);
                    mma_f16(acc_o[mi][njp * 2 + 1], pf[mi][kg2], &vf[njp][2]);
                }
        }
    }

    float inv[4];
    #pragma unroll
    for (int i = 0; i < 4; i++) {
        float z = zz[i];
        z += __shfl_xor_sync(0xffffffffu, z, 1);
        z += __shfl_xor_sync(0xffffffffu, z, 2);
        inv[i] = 1.0f / z;
    }

    #pragma unroll
    for (int mi = 0; mi < 2; mi++) {
        const int row0 = b * SEQ + half * 128 + warp_q + mi * 16 + g;
        #pragma unroll
        for (int nj = 0; nj < 8; nj++) {
            const int col = h * DHEAD + nj * 8 + 2 * t;
            *(uint32_t*)&O[(size_t)row0 * HDIM + col] =
                pack2(acc_o[mi][nj][0] * inv[mi * 2],
                      acc_o[mi][nj][1] * inv[mi * 2]);
            *(uint32_t*)&O[(size_t)(row0 + 8) * HDIM + col] =
                pack2(acc_o[mi][nj][2] * inv[mi * 2 + 1],
                      acc_o[mi][nj][3] * inv[mi * 2 + 1]);
        }
    }
}

// ---------------- embeddings + LayerNorm (vectorized, dual write) --------
__global__ __launch_bounds__(192)
void embed_ln_kernel(const int* __restrict__ ids,
                     const int* __restrict__ tids,
                     const float* __restrict__ we,
                     const float* __restrict__ pe,
                     const float* __restrict__ te,
                     const float* __restrict__ gg,
                     const float* __restrict__ bb,
                     float* __restrict__ X,
                     __half* __restrict__ Xh) {
    const int row = blockIdx.x;
    const int s   = row & (SEQ - 1);
    const int tid = threadIdx.x;
    const int id  = ids[row];
    const int tp  = tids[row];

    float4 w4 = *(const float4*)(we + (size_t)id * HDIM + tid * 4);
    float4 p4 = *(const float4*)(pe + (size_t)s  * HDIM + tid * 4);
    float4 t4 = *(const float4*)(te + (size_t)tp * HDIM + tid * 4);
    float4 v;
    v.x = w4.x + p4.x + t4.x;
    v.y = w4.y + p4.y + t4.y;
    v.z = w4.z + p4.z + t4.z;
    v.w = w4.w + p4.w + t4.w;

    float sum = v.x + v.y + v.z + v.w;
    float sq  = v.x * v.x + v.y * v.y + v.z * v.z + v.w * v.w;
    __shared__ float sa[6], sb2[6];
    int lane = tid & 31, w = tid >> 5;
    #pragma unroll
    for (int o = 16; o > 0; o >>= 1) {
        sum += __shfl_down_sync(0xffffffffu, sum, o);
        sq  += __shfl_down_sync(0xffffffffu, sq,  o);
    }
    if (lane == 0) { sa[w] = sum; sb2[w] = sq; }
    __syncthreads();
    if (tid == 0) {
        float a = 0.f, b2 = 0.f;
        for (int i = 0; i < 6; i++) { a += sa[i]; b2 += sb2[i]; }
        sa[0] = a; sb2[0] = b2;
    }
    __syncthreads();
    float mean = sa[0] * (1.0f / HDIM);
    float var  = sb2[0] * (1.0f / HDIM) - mean * mean;
    float r    = rsqrtf(var + 1e-12f);

    float4 g4 = *(const float4*)(gg + tid * 4);
    float4 b4 = *(const float4*)(bb + tid * 4);
    float4 o;
    o.x = (v.x - mean) * r * g4.x + b4.x;
    o.y = (v.y - mean) * r * g4.y + b4.y;
    o.z = (v.z - mean) * r * g4.z + b4.z;
    o.w = (v.w - mean) * r * g4.w + b4.w;
    *(float4*)(X + (size_t)row * HDIM + tid * 4) = o;
    uint2 h2 = make_uint2(pack2(o.x, o.y), pack2(o.z, o.w));
    *(uint2*)(Xh + (size_t)row * HDIM + tid * 4) = h2;
}

// ---------------- LayerNorm of pre-summed input (vectorized) -------------
__global__ __launch_bounds__(192)
void ln_kernel(float* __restrict__ X,
               const float* __restrict__ T,
               const float* __restrict__ gg,
               const float* __restrict__ bb,
               __half* __restrict__ Xh) {
    const int row = blockIdx.x;
    const int tid = threadIdx.x;

    float4 v = *(const float4*)(T + (size_t)row * HDIM + tid * 4);

    float sum = v.x + v.y + v.z + v.w;
    float sq  = v.x * v.x + v.y * v.y + v.z * v.z + v.w * v.w;
    __shared__ float sa[6], sb2[6];
    int lane = tid & 31, w = tid >> 5;
    #pragma unroll
    for (int o = 16; o > 0; o >>= 1) {
        sum += __shfl_down_sync(0xffffffffu, sum, o);
        sq  += __shfl_down_sync(0xffffffffu, sq,  o);
    }
    if (lane == 0) { sa[w] = sum; sb2[w] = sq; }
    __syncthreads();
    if (tid == 0) {
        float a = 0.f, b2 = 0.f;
        for (int i = 0; i < 6; i++) { a += sa[i]; b2 += sb2[i]; }
        sa[0] = a; sb2[0] = b2;
    }
    __syncthreads();
    float mean = sa[0] * (1.0f / HDIM);
    float var  = sb2[0] * (1.0f / HDIM) - mean * mean;
    float r    = rsqrtf(var + 1e-12f);

    float4 g4 = *(const float4*)(gg + tid * 4);
    float4 b4 = *(const float4*)(bb + tid * 4);
    float4 o;
    o.x = (v.x - mean) * r * g4.x + b4.x;
    o.y = (v.y - mean) * r * g4.y + b4.y;
    o.z = (v.z - mean) * r * g4.z + b4.z;
    o.w = (v.w - mean) * r * g4.w + b4.w;
    *(float4*)(X + (size_t)row * HDIM + tid * 4) = o;
    uint2 h2 = make_uint2(pack2(o.x, o.y), pack2(o.z, o.w));
    *(uint2*)(Xh + (size_t)row * HDIM + tid * 4) = h2;
}

// ---------------- stable valid-token compaction -------------------------
__global__ __launch_bounds__(256)
void compact_kernel(const int* __restrict__ valid,
                    const float* __restrict__ X,
                    float* __restrict__ Y) {
    const int b   = blockIdx.x;
    const int tid = threadIdx.x;
    __shared__ int sv[SEQ];
    __shared__ int pref[SEQ + 1];
    sv[tid] = valid[b * SEQ + tid];
    __syncthreads();
    if (tid == 0) {
        int acc = 0;
        for (int s = 0; s < SEQ; s++) { pref[s] = acc; acc += sv[s] ? 1 : 0; }
        pref[SEQ] = acc;
    }
    __syncthreads();
    const int count = pref[SEQ];
    for (int s = 0; s < SEQ; s++) {
        if (sv[s]) {
            int p = pref[s];
            const float* src = X + (size_t)(b * SEQ + s) * HDIM;
            float*       dst = Y + (size_t)(b * SEQ + p) * HDIM;
            for (int i = tid; i < HDIM; i += 256) dst[i] = src[i];
        }
    }
    for (int p = count; p < SEQ; p++) {
        float* dst = Y + (size_t)(b * SEQ + p) * HDIM;
        for (int i = tid; i < HDIM; i += 256) dst[i] = 0.0f;
    }
}

// ---------------- classifier + softmax over 9 labels --------------------
__global__ __launch_bounds__(256)
void cls_kernel(const float* __restrict__ Y,
                const float* __restrict__ W,
                const float* __restrict__ bias,
                float* __restrict__ out) {
    const int row = blockIdx.x;
    const int tid = threadIdx.x;
    float p[NLBL];
    #pragma unroll
    for (int j = 0; j < NLBL; j++) p[j] = 0.f;
    const float* yr = Y + (size_t)row * HDIM;
    for (int i = tid; i < HDIM; i += 256) {
        float x = yr[i];
        const float* wr = W + i * NLBL;
        #pragma unroll
        for (int j = 0; j < NLBL; j++) p[j] += x * wr[j];
    }
    __shared__ float red[NLBL][8];
    int lane = tid & 31, w = tid >> 5;
    #pragma unroll
    for (int j = 0; j < NLBL; j++) {
        float v = p[j];
        #pragma unroll
        for (int o = 16; o > 0; o >>= 1) v += __shfl_down_sync(0xffffffffu, v, o);
        if (lane == 0) red[j][w] = v;
    }
    __syncthreads();
    if (tid == 0) {
        float lg[NLBL];
        float m = -1e30f;
        for (int j = 0; j < NLBL; j++) {
            float v = bias[j];
            for (int k = 0; k < 8; k++) v += red[j][k];
            lg[j] = v;
            m = fmaxf(m, v);
        }
        float Z = 0.f;
        for (int j = 0; j < NLBL; j++) { lg[j] = expf(lg[j] - m); Z += lg[j]; }
        float inv = 1.0f / Z;
        for (int j = 0; j < NLBL; j++) out[row * NLBL + j] = lg[j] * inv;
    }
}

// ---------------- launch --------------------------------------------------
extern "C" void kernel_launch(void* const* d_in, const int* in_sizes, int n_in,
                              void* d_out, int out_size) {
    const int*   ids   = (const int*)  d_in[0];
    const int*   imask = (const int*)  d_in[1];
    const int*   tids  = (const int*)  d_in[2];
    const int*   vmask = (const int*)  d_in[3];
    const float* we    = (const float*)d_in[4];
    const float* pe    = (const float*)d_in[5];
    const float* te    = (const float*)d_in[6];
    const float* elg   = (const float*)d_in[7];
    const float* elb   = (const float*)d_in[8];
    const float* Wq    = (const float*)d_in[9];
    const float* bq    = (const float*)d_in[10];
    const float* Wk    = (const float*)d_in[11];
    const float* bk    = (const float*)d_in[12];
    const float* Wv    = (const float*)d_in[13];
    const float* bv    = (const float*)d_in[14];
    const float* Wo    = (const float*)d_in[15];
    const float* bos   = (const float*)d_in[16];
    const float* alg   = (const float*)d_in[17];
    const float* alb   = (const float*)d_in[18];
    const float* W1    = (const float*)d_in[19];
    const float* b1    = (const float*)d_in[20];
    const float* W2    = (const float*)d_in[21];
    const float* b2    = (const float*)d_in[22];
    const float* flg   = (const float*)d_in[23];
    const float* flb   = (const float*)d_in[24];
    const float* cW    = (const float*)d_in[25];
    const float* cb    = (const float*)d_in[26];
    float*       out   = (float*)d_out;

    float  *px, *pt, *pcomp;
    __half *pxh, *pqh, *pkh, *pvh, *pch, *pfh, *pwh;
    cudaGetSymbolAddress((void**)&px,    g_x);
    cudaGetSymbolAddress((void**)&pxh,   g_xh);
    cudaGetSymbolAddress((void**)&pqh,   g_qh);
    cudaGetSymbolAddress((void**)&pkh,   g_kh);
    cudaGetSymbolAddress((void**)&pvh,   g_vh);
    cudaGetSymbolAddress((void**)&pch,   g_ch);
    cudaGetSymbolAddress((void**)&pt,    g_tmp);
    cudaGetSymbolAddress((void**)&pfh,   g_fh);
    cudaGetSymbolAddress((void**)&pcomp, g_comp);
    cudaGetSymbolAddress((void**)&pwh,   g_wh);

    cudaFuncSetAttribute(attn_mma_kernel,
                         cudaFuncAttributeMaxDynamicSharedMemorySize, ATT_SMEM2);
    cudaFuncSetAttribute(gemm_kernel<1, 1>,
                         cudaFuncAttributeMaxDynamicSharedMemorySize, GEMM_SMEM);
    cudaFuncSetAttribute(gemm_kernel<3, 0>,
                         cudaFuncAttributeMaxDynamicSharedMemorySize, GEMM_SMEM);
    cudaFuncSetAttribute(gemm_kernel<2, 1>,
                         cudaFuncAttributeMaxDynamicSharedMemorySize, GEMM_SMEM);

    // ---- weight conversion pre-pass: 2 fused launches ----
    convw4_kernel<<<2048, 256>>>(Wq, Wk, Wv, Wo, pwh);
    convw2_kernel<<<2048, 256>>>(W1, W2, pwh + W1_OFF);

    embed_ln_kernel<<<NTOK, 192>>>(ids, tids, we, pe, te, elg, elb, px, pxh);

    dim3 gqkv(HDIM / BN, NTOK / BM, 3);   // (6, 32, 3) fused QKV
    dim3 g768(HDIM / BN, NTOK / BM, 1);   // (6, 32)
    dim3 gff (FF   / BN, NTOK / BM, 1);   // (24, 32)

    const int lw1 = HDIM * HDIM;
    const int lw2 = HDIM * FF;

    for (int l = 0; l < LAYERS; l++) {
        size_t bo_ = (size_t)l * HDIM;
        size_t b1o = (size_t)l * FF;
        const __half* wqp = pwh + WQ_OFF + (size_t)l * lw1;
        const __half* wkp = pwh + WK_OFF + (size_t)l * lw1;
        const __half* wvp = pwh + WV_OFF + (size_t)l * lw1;
        const __half* wop = pwh + WO_OFF + (size_t)l * lw1;
        const __half* w1p = pwh + W1_OFF + (size_t)l * lw2;
        const __half* w2p = pwh + W2_OFF + (size_t)l * lw2;

        gemm_kernel<1, 1><<<gqkv, 128, GEMM_SMEM>>>(
            NTOK, HDIM, HDIM, pxh, wqp, wkp, wvp,
            bq + bo_, bk + bo_, bv + bo_, nullptr,
            nullptr, nullptr, nullptr, pqh, pkh, pvh);

        attn_mma_kernel<<<BATCH * HEADS * 2, 128, ATT_SMEM2>>>(pqh, pkh, pvh, imask, pch);

        gemm_kernel<3, 0><<<g768, 128, GEMM_SMEM>>>(
            NTOK, HDIM, HDIM, pch, wop, wop, wop,
            bos + bo_, bos + bo_, bos + bo_, px,
            pt, pt, pt, nullptr, nullptr, nullptr);
        ln_kernel<<<NTOK, 192>>>(px, pt, alg + bo_, alb + bo_, pxh);

        gemm_kernel<2, 1><<<gff, 128, GEMM_SMEM>>>(
            NTOK, FF, HDIM, pxh, w1p, w1p, w1p,
            b1 + b1o, b1 + b1o, b1 + b1o, nullptr,
            nullptr, nullptr, nullptr, pfh, pfh, pfh);

        gemm_kernel<3, 0><<<g768, 128, GEMM_SMEM>>>(
            NTOK, HDIM, FF, pfh, w2p, w2p, w2p,
            b2 + bo_, b2 + bo_, b2 + bo_, px,
            pt, pt, pt, nullptr, nullptr, nullptr);
        ln_kernel<<<NTOK, 192>>>(px, pt, flg + bo_, flb + bo_, pxh);
    }

    compact_kernel<<<BATCH, 256>>>(vmask, px, pcomp);
    cls_kernel<<<NTOK, 256>>>(pcomp, cW, cb, out);
}

// round 16
// speedup vs baseline: 1.5004x; 1.5004x over previous
#include <cuda_runtime.h>
#include <cuda_fp16.h>
#include <math.h>
#include <stdint.h>

// ---------------- problem constants ----------------
#define HDIM   768
#define SEQ    256
#define BATCH  16
#define LAYERS 12
#define HEADS  12
#define DHEAD  64
#define FF     3072
#define NTOK   4096      // BATCH*SEQ
#define NLBL   9

// ---------------- device scratch (static; allocation-guard safe) --------
__device__ float  g_x   [NTOK * HDIM];
__device__ __half g_xh  [NTOK * HDIM];
__device__ __half g_qh  [NTOK * HDIM];
__device__ __half g_kh  [NTOK * HDIM];
__device__ __half g_vh  [NTOK * HDIM];
__device__ __half g_ch  [NTOK * HDIM];     // attention context, fp16
__device__ float  g_tmp [NTOK * HDIM];
__device__ __half g_fh  [NTOK * FF];       // FFN hidden, fp16
__device__ float  g_comp[NTOK * HDIM];

// fp16 weights, plain [L][K][N] layout (pure cast of the fp32 inputs)
#define HH (LAYERS * HDIM * HDIM)
#define HF (LAYERS * HDIM * FF)
#define WQ_OFF  0
#define WK_OFF  (HH)
#define WV_OFF  (2 * HH)
#define WO_OFF  (3 * HH)
#define W1_OFF  (4 * HH)
#define W2_OFF  (4 * HH + HF)
__device__ __half g_wh[4 * HH + 2 * HF];

// ---------------- helpers ------------------------------------------------
__device__ __forceinline__ float gelu_tanh(float x) {
    float x3 = x * x * x;
    float t  = tanhf(0.7978845608028654f * (x + 0.044715f * x3));
    return 0.5f * x * (1.0f + t);
}

__device__ __forceinline__ uint32_t pack2(float lo, float hi) {
    uint32_t u;
    asm("cvt.rn.f16x2.f32 %0, %1, %2;" : "=r"(u) : "f"(hi), "f"(lo));
    return u;
}

__device__ __forceinline__ void mma_f16(float* c, const uint32_t* a, const uint32_t* b) {
    asm volatile(
        "mma.sync.aligned.m16n8k16.row.col.f32.f16.f16.f32 "
        "{%0,%1,%2,%3}, {%4,%5,%6,%7}, {%8,%9}, {%0,%1,%2,%3};\n"
        : "+f"(c[0]), "+f"(c[1]), "+f"(c[2]), "+f"(c[3])
        : "r"(a[0]), "r"(a[1]), "r"(a[2]), "r"(a[3]), "r"(b[0]), "r"(b[1]));
}

__device__ __forceinline__ void cp_async16(uint32_t dst, const void* src) {
    asm volatile("cp.async.cg.shared.global [%0], [%1], 16;\n" :: "r"(dst), "l"(src));
}

__device__ __forceinline__ void ldsm_x4(uint32_t* r, uint32_t addr) {
    asm volatile(
        "ldmatrix.sync.aligned.m8n8.x4.shared.b16 {%0,%1,%2,%3}, [%4];"
        : "=r"(r[0]), "=r"(r[1]), "=r"(r[2]), "=r"(r[3]) : "r"(addr));
}

__device__ __forceinline__ void ldsm_x4_t(uint32_t* r, uint32_t addr) {
    asm volatile(
        "ldmatrix.sync.aligned.m8n8.x4.trans.shared.b16 {%0,%1,%2,%3}, [%4];"
        : "=r"(r[0]), "=r"(r[1]), "=r"(r[2]), "=r"(r[3]) : "r"(addr));
}

// ---------------- weight conversion: fp32 -> fp16 (fused, 2 launches) ----
__global__ __launch_bounds__(256)
void convw4_kernel(const float* __restrict__ W0, const float* __restrict__ W1_,
                   const float* __restrict__ W2_, const float* __restrict__ W3,
                   __half* __restrict__ P) {
    const int half_hh = HH / 2;
    for (int i = blockIdx.x * blockDim.x + threadIdx.x; i < 4 * half_hh;
         i += gridDim.x * blockDim.x) {
        const int reg = i / half_hh;
        const int off = i - reg * half_hh;
        const float* W = (reg == 0) ? W0 : (reg == 1) ? W1_ : (reg == 2) ? W2_ : W3;
        float2 v = ((const float2*)W)[off];
        ((uint32_t*)P)[i] = pack2(v.x, v.y);
    }
}

__global__ __launch_bounds__(256)
void convw2_kernel(const float* __restrict__ W0, const float* __restrict__ W1_,
                   __half* __restrict__ P) {
    const int half_hf = HF / 2;
    for (int i = blockIdx.x * blockDim.x + threadIdx.x; i < 2 * half_hf;
         i += gridDim.x * blockDim.x) {
        const int reg = i / half_hf;
        const int off = i - reg * half_hf;
        const float* W = (reg == 0) ? W0 : W1_;
        float2 v = ((const float2*)W)[off];
        ((uint32_t*)P)[i] = pack2(v.x, v.y);
    }
}

// ---------------- FP16 GEMM: cp.async 6-stage, 2 tiles per sync ----------
// (round-13 verified configuration: 256 threads, 8 warps, warp tile 64x32)
#define BM 128
#define BN 128
#define A_BYTES 8192
#define ST_BYTES 16384
#define NSTAGES 6
#define GEMM_SMEM (NSTAGES * ST_BYTES)    // 98304 B

__device__ __forceinline__ uint32_t swA(int r, int u) {
    return (uint32_t)(r * 64 + ((u ^ ((r >> 1) & 3)) << 4));
}
__device__ __forceinline__ uint32_t swB(int k, int u) {
    return (uint32_t)(A_BYTES + k * 256 + ((u ^ (k & 7)) << 4));
}

// EPI: 1 = +bias, 2 = +bias+gelu, 3 = +bias+residual
// OUTH: 0 = fp32 C, 1 = fp16 H
template<int EPI, int OUTH>
__global__ __launch_bounds__(256, 2)
void gemm_kernel(int M, int N, int K,
                 const __half* __restrict__ A,
                 const __half* __restrict__ B0,
                 const __half* __restrict__ B1,
                 const __half* __restrict__ B2,
                 const float* __restrict__ bias0,
                 const float* __restrict__ bias1,
                 const float* __restrict__ bias2,
                 const float* __restrict__ RES,
                 float* __restrict__ C0,
                 float* __restrict__ C1,
                 float* __restrict__ C2,
                 __half* __restrict__ H0,
                 __half* __restrict__ H1,
                 __half* __restrict__ H2) {
    extern __shared__ __align__(128) uint8_t smraw[];
    const uint32_t smem_base = (uint32_t)__cvta_generic_to_shared(smraw);

    const int z = blockIdx.z;
    const __half* Bp  = (z == 0) ? B0 : ((z == 1) ? B1 : B2);
    const float* bias = (z == 0) ? bias0 : ((z == 1) ? bias1 : bias2);
    float* C          = (z == 0) ? C0 : ((z == 1) ? C1 : C2);
    __half* H         = (z == 0) ? H0 : ((z == 1) ? H1 : H2);

    const int tid  = threadIdx.x;
    const int bx   = blockIdx.x;
    const int by   = blockIdx.y;
    const int wid  = tid >> 5;
    const int lane = tid & 31;
    const int g    = lane >> 2;
    const int t    = lane & 3;

    const int warp_m = (wid >> 2) * 64;
    const int warp_n = (wid & 3)  * 32;

    const int ar = tid >> 2;
    const int au = tid & 3;
    const int bk = tid >> 4;
    const int bu = tid & 15;

    const __half* Asrc = A + (size_t)(by * BM + ar) * K + au * 8;
    const __half* Bsrc = Bp + (size_t)bk * N + bx * BN + bu * 8;

    const uint32_t dA0 = swA(ar, au);
    const uint32_t dA1 = swA(ar + 64, au);
    const uint32_t dB0 = swB(bk, bu);
    const uint32_t dB1 = swB(bk + 16, bu);

    float acc[4][4][4];
    #pragma unroll
    for (int i = 0; i < 4; i++)
        #pragma unroll
        for (int j = 0; j < 4; j++)
            #pragma unroll
            for (int r = 0; r < 4; r++) acc[i][j][r] = 0.0f;

    auto issue = [&](int kt, int st) {
        const uint32_t sb = smem_base + st * ST_BYTES;
        cp_async16(sb + dA0, Asrc + (size_t)kt * 32);
        cp_async16(sb + dA1, Asrc + (size_t)64 * K + (size_t)kt * 32);
        cp_async16(sb + dB0, Bsrc + (size_t)(kt * 32) * N);
        cp_async16(sb + dB1, Bsrc + (size_t)(kt * 32 + 16) * N);
        asm volatile("cp.async.commit_group;\n");
    };

    const int aRowL = warp_m + (lane & 15);
    const int aUHi  = lane >> 4;
    const int bKL = (lane & 7) + ((lane >> 3) & 1) * 8;
    const int bUL = (warp_n >> 3) + ((lane >> 4) & 1);

    auto process = [&](uint32_t sb) {
        #pragma unroll
        for (int kg = 0; kg < 2; kg++) {
            uint32_t af[4][4];
            uint32_t bf[4][2];
            #pragma unroll
            for (int mi = 0; mi < 4; mi++) {
                const int r = aRowL + mi * 16;
                ldsm_x4(af[mi], sb + swA(r, kg * 2 + aUHi));
            }
            #pragma unroll
            for (int njp = 0; njp < 2; njp++) {
                uint32_t br[4];
                const int k = kg * 16 + bKL;
                ldsm_x4_t(br, sb + swB(k, bUL + njp * 2));
                bf[njp * 2    ][0] = br[0]; bf[njp * 2    ][1] = br[1];
                bf[njp * 2 + 1][0] = br[2]; bf[njp * 2 + 1][1] = br[3];
            }
            #pragma unroll
            for (int mi = 0; mi < 4; mi++)
                #pragma unroll
                for (int nj = 0; nj < 4; nj++)
                    mma_f16(acc[mi][nj], af[mi], bf[nj]);
        }
    };

    const int nk = K >> 5;    // 24 or 96, always even, >= 6
    issue(0, 0);
    issue(1, 1);
    issue(2, 2);
    issue(3, 3);

    for (int kt = 0; kt < nk; kt += 2) {
        if (kt + 2 < nk) asm volatile("cp.async.wait_group 2;\n");
        else             asm volatile("cp.async.wait_group 0;\n");
        __syncthreads();
        if (kt + 4 < nk) {
            issue(kt + 4, (kt + 4) % NSTAGES);
            issue(kt + 5, (kt + 5) % NSTAGES);
        }
        process(smem_base + (kt % NSTAGES) * ST_BYTES);
        process(smem_base + ((kt + 1) % NSTAGES) * ST_BYTES);
    }

    // ---- epilogue ----
    #pragma unroll
    for (int mi = 0; mi < 4; mi++) {
        const int r0 = by * BM + warp_m + mi * 16 + g;
        #pragma unroll
        for (int nj = 0; nj < 4; nj++) {
            const int c0 = bx * BN + warp_n + nj * 8 + 2 * t;
            float v0 = acc[mi][nj][0];
            float v1 = acc[mi][nj][1];
            float v2 = acc[mi][nj][2];
            float v3 = acc[mi][nj][3];
            {
                float bb0 = bias[c0], bb1 = bias[c0 + 1];
                v0 += bb0; v1 += bb1; v2 += bb0; v3 += bb1;
            }
            if (EPI == 2) {
                v0 = gelu_tanh(v0); v1 = gelu_tanh(v1);
                v2 = gelu_tanh(v2); v3 = gelu_tanh(v3);
            }
            if (EPI == 3) {
                v0 += RES[(size_t)(r0    ) * N + c0    ];
                v1 += RES[(size_t)(r0    ) * N + c0 + 1];
                v2 += RES[(size_t)(r0 + 8) * N + c0    ];
                v3 += RES[(size_t)(r0 + 8) * N + c0 + 1];
            }
            if (OUTH) {
                *(uint32_t*)&H[(size_t)(r0    ) * N + c0] = pack2(v0, v1);
                *(uint32_t*)&H[(size_t)(r0 + 8) * N + c0] = pack2(v2, v3);
            } else {
                C[(size_t)(r0    ) * N + c0    ] = v0;
                C[(size_t)(r0    ) * N + c0 + 1] = v1;
                C[(size_t)(r0 + 8) * N + c0    ] = v2;
                C[(size_t)(r0 + 8) * N + c0 + 1] = v3;
            }
        }
    }
}

// ---------------- tensor-core attention (2 CTAs per (b,h)) ---------------
#define ATT_Q  0
#define ATT_K  32768
#define ATT_V  65536
#define ATT_MB 98304
#define ATT_SMEM2 (98304 + 1024)

__device__ __forceinline__ uint32_t swz128(int r, int u) {
    return (uint32_t)(r * 128 + ((u ^ (r & 7)) << 4));
}

__global__ __launch_bounds__(128, 2)
void attn_mma_kernel(const __half* __restrict__ Q,
                     const __half* __restrict__ K,
                     const __half* __restrict__ V,
                     const int* __restrict__ mask,
                     __half* __restrict__ O) {
    extern __shared__ __align__(128) uint8_t smraw[];
    const uint32_t sb = (uint32_t)__cvta_generic_to_shared(smraw);
    float* mb = (float*)(smraw + ATT_MB);

    const int bx   = blockIdx.x;
    const int bh   = bx >> 1;
    const int half = bx & 1;
    const int b    = bh / HEADS;
    const int h    = bh % HEADS;
    const int tid  = threadIdx.x;
    const int wid  = tid >> 5;
    const int lane = tid & 31;
    const int g    = lane >> 2;
    const int t    = lane & 3;

    {
        const int u  = tid & 7;
        const int r0 = tid >> 3;               // 0..15
        #pragma unroll
        for (int i = 0; i < 16; i++) {
            const int r = r0 + i * 16;
            const size_t goff = (size_t)(b * SEQ + r) * HDIM + h * DHEAD + u * 8;
            cp_async16(sb + ATT_K + swz128(r, u), K + goff);
            cp_async16(sb + ATT_V + swz128(r, u), V + goff);
        }
        #pragma unroll
        for (int i = 0; i < 8; i++) {
            const int rq = r0 + i * 16;        // 0..127 local
            const size_t goff =
                (size_t)(b * SEQ + half * 128 + rq) * HDIM + h * DHEAD + u * 8;
            cp_async16(sb + ATT_Q + swz128(rq, u), Q + goff);
        }
        asm volatile("cp.async.commit_group;\n");
    }
    mb[tid]       = mask[b * SEQ + tid]       ? 0.0f : -10000.0f;
    mb[tid + 128] = mask[b * SEQ + tid + 128] ? 0.0f : -10000.0f;
    asm volatile("cp.async.wait_group 0;\n");
    __syncthreads();

    const int warp_q = wid * 32;               // local Q row base

    uint32_t qf[2][4][4];
    #pragma unroll
    for (int mi = 0; mi < 2; mi++)
        #pragma unroll
        for (int kg = 0; kg < 4; kg++)
            ldsm_x4(qf[mi][kg],
                sb + ATT_Q + swz128(warp_q + mi * 16 + (lane & 15),
                                    kg * 2 + (lane >> 4)));

    float acc_o[2][8][4];
    #pragma unroll
    for (int mi = 0; mi < 2; mi++)
        #pragma unroll
        for (int nj = 0; nj < 8; nj++)
            #pragma unroll
            for (int r = 0; r < 4; r++) acc_o[mi][nj][r] = 0.0f;
    float zz[4] = {0.f, 0.f, 0.f, 0.f};

    for (int kc = 0; kc < 4; kc++) {
        const int key0 = kc * 64;
        float s[2][8][4];
        #pragma unroll
        for (int mi = 0; mi < 2; mi++)
            #pragma unroll
            for (int nj = 0; nj < 8; nj++)
                #pragma unroll
                for (int r = 0; r < 4; r++) s[mi][nj][r] = 0.0f;

        #pragma unroll
        for (int kg = 0; kg < 4; kg++) {
            uint32_t kf[4][4];
            #pragma unroll
            for (int njp = 0; njp < 4; njp++) {
                const int r = key0 + njp * 16 + (lane & 7) + 8 * ((lane >> 4) & 1);
                const int u = kg * 2 + ((lane >> 3) & 1);
                ldsm_x4(kf[njp], sb + ATT_K + swz128(r, u));
            }
            #pragma unroll
            for (int mi = 0; mi < 2; mi++)
                #pragma unroll
                for (int njp = 0; njp < 4; njp++) {
                    mma_f16(s[mi][njp * 2    ], qf[mi][kg], &kf[njp][0]);
                    mma_f16(s[mi][njp * 2 + 1], qf[mi][kg], &kf[njp][2]);
                }
        }

        uint32_t pf[2][4][4];
        #pragma unroll
        for (int mi = 0; mi < 2; mi++) {
            #pragma unroll
            for (int nj = 0; nj < 8; nj++) {
                const float m0 = mb[key0 + nj * 8 + 2 * t];
                const float m1 = mb[key0 + nj * 8 + 2 * t + 1];
                float p0 = __expf(s[mi][nj][0] * 0.125f + m0);
                float p1 = __expf(s[mi][nj][1] * 0.125f + m1);
                float p2 = __expf(s[mi][nj][2] * 0.125f + m0);
                float p3 = __expf(s[mi][nj][3] * 0.125f + m1);
                zz[mi * 2    ] += p0 + p1;
                zz[mi * 2 + 1] += p2 + p3;
                const int kg2 = nj >> 1;
                const int hi  = nj & 1;
                pf[mi][kg2][hi * 2    ] = pack2(p0, p1);
                pf[mi][kg2][hi * 2 + 1] = pack2(p2, p3);
            }
        }

        #pragma unroll
        for (int kg2 = 0; kg2 < 4; kg2++) {
            uint32_t vf[4][4];
            #pragma unroll
            for (int njp = 0; njp < 4; njp++) {
                const int r = key0 + kg2 * 16 + (lane & 7) + 8 * ((lane >> 3) & 1);
                const int u = njp * 2 + ((lane >> 4) & 1);
                ldsm_x4_t(vf[njp], sb + ATT_V + swz128(r, u));
            }
            #pragma unroll
            for (int mi = 0; mi < 2; mi++)
                #pragma unroll
                for (int njp = 0; njp < 4; njp++) {
                    mma_f16(acc_o[mi][njp * 2    ], pf[mi][kg2], &vf[njp][0]);
                    mma_f16(acc_o[mi][njp * 2 + 1], pf[mi][kg2], &vf[njp][2]);
                }
        }
    }

    float inv[4];
    #pragma unroll
    for (int i = 0; i < 4; i++) {
        float z = zz[i];
        z += __shfl_xor_sync(0xffffffffu, z, 1);
        z += __shfl_xor_sync(0xffffffffu, z, 2);
        inv[i] = 1.0f / z;
    }

    #pragma unroll
    for (int mi = 0; mi < 2; mi++) {
        const int row0 = b * SEQ + half * 128 + warp_q + mi * 16 + g;
        #pragma unroll
        for (int nj = 0; nj < 8; nj++) {
            const int col = h * DHEAD + nj * 8 + 2 * t;
            *(uint32_t*)&O[(size_t)row0 * HDIM + col] =
                pack2(acc_o[mi][nj][0] * inv[mi * 2],
                      acc_o[mi][nj][1] * inv[mi * 2]);
            *(uint32_t*)&O[(size_t)(row0 + 8) * HDIM + col] =
                pack2(acc_o[mi][nj][2] * inv[mi * 2 + 1],
                      acc_o[mi][nj][3] * inv[mi * 2 + 1]);
        }
    }
}

// ---------------- embeddings + LayerNorm (vectorized, dual write) --------
__global__ __launch_bounds__(192)
void embed_ln_kernel(const int* __restrict__ ids,
                     const int* __restrict__ tids,
                     const float* __restrict__ we,
                     const float* __restrict__ pe,
                     const float* __restrict__ te,
                     const float* __restrict__ gg,
                     const float* __restrict__ bb,
                     float* __restrict__ X,
                     __half* __restrict__ Xh) {
    const int row = blockIdx.x;
    const int s   = row & (SEQ - 1);
    const int tid = threadIdx.x;
    const int id  = ids[row];
    const int tp  = tids[row];

    float4 w4 = *(const float4*)(we + (size_t)id * HDIM + tid * 4);
    float4 p4 = *(const float4*)(pe + (size_t)s  * HDIM + tid * 4);
    float4 t4 = *(const float4*)(te + (size_t)tp * HDIM + tid * 4);
    float4 v;
    v.x = w4.x + p4.x + t4.x;
    v.y = w4.y + p4.y + t4.y;
    v.z = w4.z + p4.z + t4.z;
    v.w = w4.w + p4.w + t4.w;

    float sum = v.x + v.y + v.z + v.w;
    float sq  = v.x * v.x + v.y * v.y + v.z * v.z + v.w * v.w;
    __shared__ float sa[6], sb2[6];
    int lane = tid & 31, w = tid >> 5;
    #pragma unroll
    for (int o = 16; o > 0; o >>= 1) {
        sum += __shfl_down_sync(0xffffffffu, sum, o);
        sq  += __shfl_down_sync(0xffffffffu, sq,  o);
    }
    if (lane == 0) { sa[w] = sum; sb2[w] = sq; }
    __syncthreads();
    if (tid == 0) {
        float a = 0.f, b2 = 0.f;
        for (int i = 0; i < 6; i++) { a += sa[i]; b2 += sb2[i]; }
        sa[0] = a; sb2[0] = b2;
    }
    __syncthreads();
    float mean = sa[0] * (1.0f / HDIM);
    float var  = sb2[0] * (1.0f / HDIM) - mean * mean;
    float r    = rsqrtf(var + 1e-12f);

    float4 g4 = *(const float4*)(gg + tid * 4);
    float4 b4 = *(const float4*)(bb + tid * 4);
    float4 o;
    o.x = (v.x - mean) * r * g4.x + b4.x;
    o.y = (v.y - mean) * r * g4.y + b4.y;
    o.z = (v.z - mean) * r * g4.z + b4.z;
    o.w = (v.w - mean) * r * g4.w + b4.w;
    *(float4*)(X + (size_t)row * HDIM + tid * 4) = o;
    uint2 h2 = make_uint2(pack2(o.x, o.y), pack2(o.z, o.w));
    *(uint2*)(Xh + (size_t)row * HDIM + tid * 4) = h2;
}

// ---------------- LayerNorm of pre-summed input (vectorized) -------------
__global__ __launch_bounds__(192)
void ln_kernel(float* __restrict__ X,
               const float* __restrict__ T,
               const float* __restrict__ gg,
               const float* __restrict__ bb,
               __half* __restrict__ Xh) {
    const int row = blockIdx.x;
    const int tid = threadIdx.x;

    float4 v = *(const float4*)(T + (size_t)row * HDIM + tid * 4);

    float sum = v.x + v.y + v.z + v.w;
    float sq  = v.x * v.x + v.y * v.y + v.z * v.z + v.w * v.w;
    __shared__ float sa[6], sb2[6];
    int lane = tid & 31, w = tid >> 5;
    #pragma unroll
    for (int o = 16; o > 0; o >>= 1) {
        sum += __shfl_down_sync(0xffffffffu, sum, o);
        sq  += __shfl_down_sync(0xffffffffu, sq,  o);
    }
    if (lane == 0) { sa[w] = sum; sb2[w] = sq; }
    __syncthreads();
    if (tid == 0) {
        float a = 0.f, b2 = 0.f;
        for (int i = 0; i < 6; i++) { a += sa[i]; b2 += sb2[i]; }
        sa[0] = a; sb2[0] = b2;
    }
    __syncthreads();
    float mean = sa[0] * (1.0f / HDIM);
    float var  = sb2[0] * (1.0f / HDIM) - mean * mean;
    float r    = rsqrtf(var + 1e-12f);

    float4 g4 = *(const float4*)(gg + tid * 4);
    float4 b4 = *(const float4*)(bb + tid * 4);
    float4 o;
    o.x = (v.x - mean) * r * g4.x + b4.x;
    o.y = (v.y - mean) * r * g4.y + b4.y;
    o.z = (v.z - mean) * r * g4.z + b4.z;
    o.w = (v.w - mean) * r * g4.w + b4.w;
    *(float4*)(X + (size_t)row * HDIM + tid * 4) = o;
    uint2 h2 = make_uint2(pack2(o.x, o.y), pack2(o.z, o.w));
    *(uint2*)(Xh + (size_t)row * HDIM + tid * 4) = h2;
}

// ---------------- stable valid-token compaction (float4) -----------------
__global__ __launch_bounds__(256)
void compact_kernel(const int* __restrict__ valid,
                    const float* __restrict__ X,
                    float* __restrict__ Y) {
    const int b   = blockIdx.x;
    const int tid = threadIdx.x;
    __shared__ int sv[SEQ];
    __shared__ int pref[SEQ + 1];
    sv[tid] = valid[b * SEQ + tid];
    __syncthreads();
    if (tid == 0) {
        int acc = 0;
        for (int s = 0; s < SEQ; s++) { pref[s] = acc; acc += sv[s] ? 1 : 0; }
        pref[SEQ] = acc;
    }
    __syncthreads();
    const int count = pref[SEQ];
    const int nf4 = HDIM / 4;   // 192
    for (int s = 0; s < SEQ; s++) {
        if (sv[s]) {
            int p = pref[s];
            const float4* src = (const float4*)(X + (size_t)(b * SEQ + s) * HDIM);
            float4*       dst = (float4*)(Y + (size_t)(b * SEQ + p) * HDIM);
            for (int i = tid; i < nf4; i += 256) dst[i] = src[i];
        }
    }
    const float4 z4 = make_float4(0.f, 0.f, 0.f, 0.f);
    for (int p = count; p < SEQ; p++) {
        float4* dst = (float4*)(Y + (size_t)(b * SEQ + p) * HDIM);
        for (int i = tid; i < nf4; i += 256) dst[i] = z4;
    }
}

// ---------------- classifier + softmax over 9 labels (float4 loads) ------
__global__ __launch_bounds__(256)
void cls_kernel(const float* __restrict__ Y,
                const float* __restrict__ W,
                const float* __restrict__ bias,
                float* __restrict__ out) {
    const int row = blockIdx.x;
    const int tid = threadIdx.x;
    float p[NLBL];
    #pragma unroll
    for (int j = 0; j < NLBL; j++) p[j] = 0.f;
    const float* yr = Y + (size_t)row * HDIM;
    // 192 float4 per row; threads 0..191 take one each
    if (tid < HDIM / 4) {
        float4 x4 = *(const float4*)(yr + tid * 4);
        const float* wr = W + (size_t)tid * 4 * NLBL;
        #pragma unroll
        for (int j = 0; j < NLBL; j++)
            p[j] = x4.x * wr[j] + x4.y * wr[NLBL + j]
                 + x4.z * wr[2 * NLBL + j] + x4.w * wr[3 * NLBL + j];
    }
    __shared__ float red[NLBL][8];
    int lane = tid & 31, w = tid >> 5;
    #pragma unroll
    for (int j = 0; j < NLBL; j++) {
        float v = p[j];
        #pragma unroll
        for (int o = 16; o > 0; o >>= 1) v += __shfl_down_sync(0xffffffffu, v, o);
        if (lane == 0) red[j][w] = v;
    }
    __syncthreads();
    if (tid == 0) {
        float lg[NLBL];
        float m = -1e30f;
        for (int j = 0; j < NLBL; j++) {
            float v = bias[j];
            for (int k = 0; k < 8; k++) v += red[j][k];
            lg[j] = v;
            m = fmaxf(m, v);
        }
        float Z = 0.f;
        for (int j = 0; j < NLBL; j++) { lg[j] = expf(lg[j] - m); Z += lg[j]; }
        float inv = 1.0f / Z;
        for (int j = 0; j < NLBL; j++) out[row * NLBL + j] = lg[j] * inv;
    }
}

// ---------------- launch --------------------------------------------------
extern "C" void kernel_launch(void* const* d_in, const int* in_sizes, int n_in,
                              void* d_out, int out_size) {
    const int*   ids   = (const int*)  d_in[0];
    const int*   imask = (const int*)  d_in[1];
    const int*   tids  = (const int*)  d_in[2];
    const int*   vmask = (const int*)  d_in[3];
    const float* we    = (const float*)d_in[4];
    const float* pe    = (const float*)d_in[5];
    const float* te    = (const float*)d_in[6];
    const float* elg   = (const float*)d_in[7];
    const float* elb   = (const float*)d_in[8];
    const float* Wq    = (const float*)d_in[9];
    const float* bq    = (const float*)d_in[10];
    const float* Wk    = (const float*)d_in[11];
    const float* bk    = (const float*)d_in[12];
    const float* Wv    = (const float*)d_in[13];
    const float* bv    = (const float*)d_in[14];
    const float* Wo    = (const float*)d_in[15];
    const float* bos   = (const float*)d_in[16];
    const float* alg   = (const float*)d_in[17];
    const float* alb   = (const float*)d_in[18];
    const float* W1    = (const float*)d_in[19];
    const float* b1    = (const float*)d_in[20];
    const float* W2    = (const float*)d_in[21];
    const float* b2    = (const float*)d_in[22];
    const float* flg   = (const float*)d_in[23];
    const float* flb   = (const float*)d_in[24];
    const float* cW    = (const float*)d_in[25];
    const float* cb    = (const float*)d_in[26];
    float*       out   = (float*)d_out;

    float  *px, *pt, *pcomp;
    __half *pxh, *pqh, *pkh, *pvh, *pch, *pfh, *pwh;
    cudaGetSymbolAddress((void**)&px,    g_x);
    cudaGetSymbolAddress((void**)&pxh,   g_xh);
    cudaGetSymbolAddress((void**)&pqh,   g_qh);
    cudaGetSymbolAddress((void**)&pkh,   g_kh);
    cudaGetSymbolAddress((void**)&pvh,   g_vh);
    cudaGetSymbolAddress((void**)&pch,   g_ch);
    cudaGetSymbolAddress((void**)&pt,    g_tmp);
    cudaGetSymbolAddress((void**)&pfh,   g_fh);
    cudaGetSymbolAddress((void**)&pcomp, g_comp);
    cudaGetSymbolAddress((void**)&pwh,   g_wh);

    cudaFuncSetAttribute(attn_mma_kernel,
                         cudaFuncAttributeMaxDynamicSharedMemorySize, ATT_SMEM2);
    cudaFuncSetAttribute(gemm_kernel<1, 1>,
                         cudaFuncAttributeMaxDynamicSharedMemorySize, GEMM_SMEM);
    cudaFuncSetAttribute(gemm_kernel<3, 0>,
                         cudaFuncAttributeMaxDynamicSharedMemorySize, GEMM_SMEM);
    cudaFuncSetAttribute(gemm_kernel<2, 1>,
                         cudaFuncAttributeMaxDynamicSharedMemorySize, GEMM_SMEM);

    // ---- weight conversion pre-pass: 2 fused launches ----
    convw4_kernel<<<2048, 256>>>(Wq, Wk, Wv, Wo, pwh);
    convw2_kernel<<<2048, 256>>>(W1, W2, pwh + W1_OFF);

    embed_ln_kernel<<<NTOK, 192>>>(ids, tids, we, pe, te, elg, elb, px, pxh);

    dim3 gqkv(HDIM / BN, NTOK / BM, 3);   // (6, 32, 3) fused QKV
    dim3 g768(HDIM / BN, NTOK / BM, 1);   // (6, 32)
    dim3 gff (FF   / BN, NTOK / BM, 1);   // (24, 32)

    const int lw1 = HDIM * HDIM;
    const int lw2 = HDIM * FF;

    for (int l = 0; l < LAYERS; l++) {
        size_t bo_ = (size_t)l * HDIM;
        size_t b1o = (size_t)l * FF;
        const __half* wqp = pwh + WQ_OFF + (size_t)l * lw1;
        const __half* wkp = pwh + WK_OFF + (size_t)l * lw1;
        const __half* wvp = pwh + WV_OFF + (size_t)l * lw1;
        const __half* wop = pwh + WO_OFF + (size_t)l * lw1;
        const __half* w1p = pwh + W1_OFF + (size_t)l * lw2;
        const __half* w2p = pwh + W2_OFF + (size_t)l * lw2;

        gemm_kernel<1, 1><<<gqkv, 256, GEMM_SMEM>>>(
            NTOK, HDIM, HDIM, pxh, wqp, wkp, wvp,
            bq + bo_, bk + bo_, bv + bo_, nullptr,
            nullptr, nullptr, nullptr, pqh, pkh, pvh);

        attn_mma_kernel<<<BATCH * HEADS * 2, 128, ATT_SMEM2>>>(pqh, pkh, pvh, imask, pch);

        gemm_kernel<3, 0><<<g768, 256, GEMM_SMEM>>>(
            NTOK, HDIM, HDIM, pch, wop, wop, wop,
            bos + bo_, bos + bo_, bos + bo_, px,
            pt, pt, pt, nullptr, nullptr, nullptr);
        ln_kernel<<<NTOK, 192>>>(px, pt, alg + bo_, alb + bo_, pxh);

        gemm_kernel<2, 1><<<gff, 256, GEMM_SMEM>>>(
            NTOK, FF, HDIM, pxh, w1p, w1p, w1p,
            b1 + b1o, b1 + b1o, b1 + b1o, nullptr,
            nullptr, nullptr, nullptr, pfh, pfh, pfh);

        gemm_kernel<3, 0><<<g768, 256, GEMM_SMEM>>>(
            NTOK, HDIM, FF, pfh, w2p, w2p, w2p,
            b2 + bo_, b2 + bo_, b2 + bo_, px,
            pt, pt, pt, nullptr, nullptr, nullptr);
        ln_kernel<<<NTOK, 192>>>(px, pt, flg + bo_, flb + bo_, pxh);
    }

    compact_kernel<<<BATCH, 256>>>(vmask, px, pcomp);
    cls_kernel<<<NTOK, 256>>>(pcomp, cW, cb, out);
}